// round 12
// baseline (speedup 1.0000x reference)
#include <cuda_runtime.h>
#include <cuda_fp16.h>
#include <cstdint>

// ---------------------------------------------------------------------------
// TriXLinear (sm_103 baseline PTX; tensor path = mma.sync m16n8k16 f16).
//   out = (x @ sign(W)^T) * scales * gate_mask
// x -> fp16 (norm rel err ~2.1e-4), W -> +-1 fp16 (exact). Gated-row GEMM.
// R12: A-gather kernel DELETED — the GEMM gathers gated rows straight from
// row-major fp16 x via cp.async (8 threads/row, coalesced 128B segments),
// completion folded into the stage's full mbarrier (count 128 + expect_tx
// arrive). Gate compaction is per-part (8 blocks, no cross-block atomics)
// inside the single merged prep kernel; GEMM prologue builds the prefix.
// GEMM core unchanged: warp 64x64, block 128x128, 3 stages, 2 CTAs/SM.
// ---------------------------------------------------------------------------

#define MDIM 4096
#define NDIM 4096
#define KDIM 4096

#define NKT 64                          // K stages (64 fp16 = 128B rows)
#define STAGES 3
#define STAGE_BYTES 32768               // A 16K + B 16K
#define SMEM_SC   64                    // scales (512B)
#define SMEM_SROW 576                   // gathered row ids (512B)
#define SMEM_PRE  1088                  // part prefix (9 ints)
#define SMEM_ST   2048
#define SMEM_TOTAL (SMEM_ST + STAGES * STAGE_BYTES)   // 100352 -> 2 CTAs/SM
// mbarriers: full[s] at sb+8s, empty[s] at sb+24+8s  (s = 0..2)

// merged-prep partition
#define COMPACT_BLKS 8
#define QUANT_BLKS   8192
#define SIGNW_BLKS   8192
#define ZERO_BLKS    16384
#define PREP_BLKS (COMPACT_BLKS + QUANT_BLKS + SIGNW_BLKS + ZERO_BLKS)

// ------------------------------- scratch -----------------------------------
__device__ __align__(256) __half g_Xh[(size_t)MDIM * KDIM];           // 32MB
__device__ __align__(1024) unsigned char g_Wt[(size_t)32 * 1024 * 1024];
__device__ int g_cntp[4][8];            // per-tile per-part gated-row counts
__device__ int g_rows_part[4][8][512];  // per-part compacted row ids

// ------------------------------ PTX helpers --------------------------------
__device__ __forceinline__ uint32_t smem_u32(const void* p) {
    uint32_t a;
    asm("{ .reg .u64 t; cvta.to.shared.u64 t, %1; cvt.u32.u64 %0, t; }"
        : "=r"(a) : "l"(p));
    return a;
}
__device__ __forceinline__ uint32_t elect_one() {
    uint32_t p;
    asm volatile("{ .reg .pred p; elect.sync _|p, 0xFFFFFFFF; selp.b32 %0,1,0,p; }"
                 : "=r"(p));
    return p;
}
__device__ __forceinline__ void mbar_init(uint32_t mb, uint32_t cnt) {
    asm volatile("mbarrier.init.shared.b64 [%0], %1;" :: "r"(mb), "r"(cnt) : "memory");
}
__device__ __forceinline__ void mbar_expect_tx(uint32_t mb, uint32_t bytes) {
    asm volatile("mbarrier.arrive.expect_tx.shared.b64 _, [%0], %1;"
                 :: "r"(mb), "r"(bytes) : "memory");
}
__device__ __forceinline__ void mbar_arrive(uint32_t mb) {
    asm volatile("mbarrier.arrive.shared.b64 _, [%0];" :: "r"(mb) : "memory");
}
__device__ __forceinline__ void mbar_wait(uint32_t mb, uint32_t parity) {
    asm volatile(
        "{\n\t.reg .pred P;\n\t"
        "WL_%=:\n\t"
        "mbarrier.try_wait.parity.acquire.cta.shared::cta.b64 P, [%0], %1, 0x989680;\n\t"
        "@P bra.uni WD_%=;\n\t"
        "bra.uni WL_%=;\n\t"
        "WD_%=:\n\t}"
        :: "r"(mb), "r"(parity) : "memory");
}
__device__ __forceinline__ void bulk_g2s(uint32_t dst, const void* src,
                                         uint32_t bytes, uint32_t mb) {
    asm volatile(
        "cp.async.bulk.shared::cta.global.mbarrier::complete_tx::bytes "
        "[%0], [%1], %2, [%3];"
        :: "r"(dst), "l"(src), "r"(bytes), "r"(mb) : "memory");
}
__device__ __forceinline__ void cp_async16(uint32_t dst, const void* src) {
    asm volatile("cp.async.cg.shared.global [%0], [%1], 16;"
                 :: "r"(dst), "l"(src) : "memory");
}
__device__ __forceinline__ void cp_arrive_noinc(uint32_t mb) {
    asm volatile("cp.async.mbarrier.arrive.noinc.shared::cta.b64 [%0];"
                 :: "r"(mb) : "memory");
}
__device__ __forceinline__ void ldm_x4(uint32_t* r, uint32_t addr) {
    asm volatile("ldmatrix.sync.aligned.m8n8.x4.shared.b16 {%0,%1,%2,%3}, [%4];"
                 : "=r"(r[0]), "=r"(r[1]), "=r"(r[2]), "=r"(r[3]) : "r"(addr));
}
__device__ __forceinline__ void hmma(float* c, const uint32_t* a,
                                     uint32_t b0, uint32_t b1) {
    asm volatile(
        "mma.sync.aligned.m16n8k16.row.col.f32.f16.f16.f32 "
        "{%0,%1,%2,%3}, {%4,%5,%6,%7}, {%8,%9}, {%0,%1,%2,%3};"
        : "+f"(c[0]), "+f"(c[1]), "+f"(c[2]), "+f"(c[3])
        : "r"(a[0]), "r"(a[1]), "r"(a[2]), "r"(a[3]), "r"(b0), "r"(b1));
}

// ------------------------------ merged prep ---------------------------------
// blockIdx.x partition:
//   [0, 8)        per-part gate compaction (part = 512 rows, own counters)
//   [8, 8200)     quant_x: x f32 -> fp16 row-major (8 elems/thread)
//   [8200, 16392) sign_w -> fp16 swizzled tiles
//   [16392, ...)  zero ungated (row, tile) out blocks
__global__ __launch_bounds__(256) void prep_merged(
    const float* __restrict__ x,
    const float* __restrict__ w,
    const int* __restrict__ gate,
    float* __restrict__ out) {
    const int b = blockIdx.x;
    const int tid = threadIdx.x;

    if (b < COMPACT_BLKS) {
        // ---- per-part compaction: rows [p*512, p*512+512) ----
        const int p = b;
        __shared__ int scnt[4];
        if (tid < 4) scnt[tid] = 0;
        __syncthreads();
        int lane = tid & 31;
#pragma unroll
        for (int h = 0; h < 2; h++) {
            int r = p * 512 + h * 256 + tid;
#pragma unroll
            for (int t = 0; t < 4; t++) {
                bool pred = (gate[r * 4 + t] != 0);
                unsigned mask = __ballot_sync(0xFFFFFFFFu, pred);
                int cnt = __popc(mask);
                int base = 0;
                if (lane == 0 && cnt) base = atomicAdd(&scnt[t], cnt);
                base = __shfl_sync(0xFFFFFFFFu, base, 0);
                if (pred) {
                    int rank = __popc(mask & ((1u << lane) - 1u));
                    g_rows_part[t][p][base + rank] = r;
                }
            }
        }
        __syncthreads();
        if (tid < 4) g_cntp[tid][p] = scnt[tid];
    } else if (b < COMPACT_BLKS + QUANT_BLKS) {
        // ---- quant_x: f32 -> fp16 row-major ----
        size_t i = ((size_t)(b - COMPACT_BLKS) * 256 + tid) * 8;
        const float4* pp = reinterpret_cast<const float4*>(x + i);
        float4 v0 = pp[0], v1 = pp[1];
        __half h[8];
        h[0] = __float2half_rn(v0.x); h[1] = __float2half_rn(v0.y);
        h[2] = __float2half_rn(v0.z); h[3] = __float2half_rn(v0.w);
        h[4] = __float2half_rn(v1.x); h[5] = __float2half_rn(v1.y);
        h[6] = __float2half_rn(v1.z); h[7] = __float2half_rn(v1.w);
        *reinterpret_cast<uint4*>(g_Xh + i) = *reinterpret_cast<uint4*>(h);
    } else if (b < COMPACT_BLKS + QUANT_BLKS + SIGNW_BLKS) {
        // ---- sign(W) -> fp16 swizzled tiles ----
        size_t idx = (size_t)(b - COMPACT_BLKS - QUANT_BLKS) * 256 + tid;
        int row = (int)(idx >> 9);
        int k0  = ((int)idx & 511) * 8;
        const float4* pp = reinterpret_cast<const float4*>(w + (size_t)row * KDIM + k0);
        float4 v0 = pp[0], v1 = pp[1];
        float f[8] = {v0.x, v0.y, v0.z, v0.w, v1.x, v1.y, v1.z, v1.w};
        __half s[8];
#pragma unroll
        for (int j = 0; j < 8; j++)
            s[j] = __float2half_rn((f[j] > 0.f) ? 1.f : ((f[j] < 0.f) ? -1.f : 0.f));
        int nb = row >> 7, r = row & 127, kblk = k0 >> 6;
        int c = (k0 & 63) >> 3;
        size_t off = (((size_t)(nb * 64 + kblk)) << 14) +
                     (size_t)r * 128 + ((size_t)(c ^ (r & 7)) << 4);
        *reinterpret_cast<uint4*>(g_Wt + off) = *reinterpret_cast<uint4*>(s);
    } else {
        // ---- zero ungated (row, tile) out blocks ----
        int bid = b - (COMPACT_BLKS + QUANT_BLKS + SIGNW_BLKS);
        int r = bid >> 2, t = bid & 3;
        if (gate[r * 4 + t] != 0) return;
        float4 z = {0.f, 0.f, 0.f, 0.f};
        reinterpret_cast<float4*>(out + (size_t)r * NDIM + t * 1024)[tid] = z;
    }
}

// ------------------------------ GEMM kernel ---------------------------------
// grid (8 nblk, 32 mblk, 4 t), 128 threads, warp grid 2(M) x 2(N), warp 64x64.
// A: gathered in-mainloop via cp.async from g_Xh (srow in smem).
// B: bulk-TMA from pre-swizzled g_Wt. full[s] count = 129 (128 cp + expect_tx).

__global__ __launch_bounds__(128, 2) void trix_hmma(
    const float* __restrict__ scales,
    float* __restrict__ out) {
    const int t = blockIdx.z, mblk = blockIdx.y, nblk = blockIdx.x;

    extern __shared__ char smem[];
    const uint32_t sb = smem_u32(smem);
    const int tid = threadIdx.x;
    const int warp = tid >> 5, lane = tid & 31;
    const int wm = warp >> 1, wn = warp & 1;
    const int n0 = t * 1024 + nblk * 128;
    const int nb = t * 8 + nblk;

    int* pre = reinterpret_cast<int*>(smem + SMEM_PRE);
    int* srow = reinterpret_cast<int*>(smem + SMEM_SROW);

    reinterpret_cast<float*>(smem + SMEM_SC)[tid] = scales[n0 + tid];
    if (tid == 0) {
        int acc = 0;
#pragma unroll
        for (int p = 0; p < 8; p++) { pre[p] = acc; acc += g_cntp[t][p]; }
        pre[8] = acc;
#pragma unroll
        for (int s = 0; s < STAGES; s++) {
            mbar_init(sb + 8u * s, 129);      // full: 128 cp + expect_tx arrive
            mbar_init(sb + 24u + 8u * s, 4);  // empty: 4 warp arrivals
        }
    }
    __syncthreads();

    const int cnt = pre[8];
    if (mblk * 128 >= cnt) return;

    // build srow[128] for this mblk (clamped; epilogue re-guards vs cnt)
    {
        int gidx = mblk * 128 + tid;
        if (gidx >= cnt) gidx = cnt - 1;
        int p = 0;
#pragma unroll
        for (int q = 1; q < 8; q++) p += (gidx >= pre[q]) ? 1 : 0;
        srow[tid] = g_rows_part[t][p][gidx - pre[p]];
    }
    __syncthreads();

    const unsigned char* bSrc = g_Wt + ((size_t)nb << 20);
    const int jj = tid >> 3, cc = tid & 7;     // 16 rows/pass x 8 chunks

    auto issueA = [&](int s, int kt) {
        uint32_t stA = sb + SMEM_ST + s * STAGE_BYTES;
#pragma unroll
        for (int p = 0; p < 8; p++) {
            int r = jj + p * 16;
            int row = srow[r];
            const char* src = reinterpret_cast<const char*>(g_Xh) +
                              ((size_t)row << 13) + (kt << 7) + (cc << 4);
            uint32_t dst = stA + (uint32_t)r * 128 +
                           ((uint32_t)(cc ^ (r & 7)) << 4);
            cp_async16(dst, src);
        }
        cp_arrive_noinc(sb + 8u * s);
    };
    auto fillB = [&](int s, int kt) {
        uint32_t mb = sb + 8u * s;
        mbar_expect_tx(mb, 16384);
        bulk_g2s(sb + SMEM_ST + s * STAGE_BYTES + 16384,
                 bSrc + ((size_t)kt << 14), 16384, mb);
    };
    const bool prod = (warp == 0) && elect_one();
#pragma unroll
    for (int s = 0; s < STAGES; s++) {
        issueA(s, s);
        if (prod) fillB(s, s);
    }

    // ldmatrix addressing
    int aR[4], bR[4];
#pragma unroll
    for (int ms = 0; ms < 4; ms++) aR[ms] = wm * 64 + ms * 16 + (lane & 15);
    const int aCadd = lane >> 4;
#pragma unroll
    for (int nq = 0; nq < 4; nq++)
        bR[nq] = wn * 64 + nq * 16 + (lane & 7) + ((lane >> 4) << 3);
    const int bCadd = (lane >> 3) & 1;

    float d[4][8][4];
#pragma unroll
    for (int a = 0; a < 4; a++)
#pragma unroll
        for (int b = 0; b < 8; b++)
#pragma unroll
            for (int c = 0; c < 4; c++) d[a][b][c] = 0.f;

    for (int kt = 0; kt < NKT; kt++) {
        const int s = kt % 3;
        const uint32_t ph = (uint32_t)((kt / 3) & 1);
        mbar_wait(sb + 8u * s, ph);                       // A cp + B tx done
        const uint32_t st = sb + SMEM_ST + s * STAGE_BYTES;
#pragma unroll
        for (int ks = 0; ks < 4; ks++) {
            uint32_t a[4][4], bf[4][4];
#pragma unroll
            for (int ms = 0; ms < 4; ms++) {
                uint32_t off = aR[ms] * 128 +
                               (((ks * 2 + aCadd) ^ (aR[ms] & 7)) << 4);
                ldm_x4(a[ms], st + off);
            }
#pragma unroll
            for (int nq = 0; nq < 4; nq++) {
                uint32_t off = bR[nq] * 128 +
                               (((ks * 2 + bCadd) ^ (bR[nq] & 7)) << 4);
                ldm_x4(bf[nq], st + 16384 + off);
            }
#pragma unroll
            for (int ms = 0; ms < 4; ms++)
#pragma unroll
                for (int nq = 0; nq < 4; nq++) {
                    hmma(d[ms][nq * 2],     a[ms], bf[nq][0], bf[nq][1]);
                    hmma(d[ms][nq * 2 + 1], a[ms], bf[nq][2], bf[nq][3]);
                }
        }
        if (elect_one()) mbar_arrive(sb + 24u + 8u * s);  // warp consumed
        if (kt + STAGES < NKT) {
            mbar_wait(sb + 24u + 8u * s, ph);             // stage fully free
            issueA(s, kt + STAGES);
            if (prod) fillB(s, kt + STAGES);
        }
    }

    // epilogue: out = acc * scales[col] for gated rows (srow cached in smem)
    const float* sSc = reinterpret_cast<const float*>(smem + SMEM_SC);
#pragma unroll
    for (int ms = 0; ms < 4; ms++) {
#pragma unroll
        for (int half = 0; half < 2; half++) {
            int j = wm * 64 + ms * 16 + (lane >> 2) + half * 8;
            if (mblk * 128 + j >= cnt) continue;
            int row = srow[j];
            float* orow = out + (size_t)row * NDIM + n0;
#pragma unroll
            for (int ns = 0; ns < 8; ns++) {
                int col = wn * 64 + ns * 8 + (lane & 3) * 2;
                float2 v;
                v.x = d[ms][ns][half * 2]     * sSc[col];
                v.y = d[ms][ns][half * 2 + 1] * sSc[col + 1];
                *reinterpret_cast<float2*>(orow + col) = v;
            }
        }
    }
}

// ------------------------------ launch --------------------------------------

extern "C" void kernel_launch(void* const* d_in, const int* in_sizes, int n_in,
                              void* d_out, int out_size) {
    const float* x      = (const float*)d_in[0];
    const int*   gate   = (const int*)d_in[1];
    const float* weight = (const float*)d_in[2];
    const float* scales = (const float*)d_in[3];
    float* out = (float*)d_out;

    cudaFuncSetAttribute(trix_hmma,
                         cudaFuncAttributeMaxDynamicSharedMemorySize, SMEM_TOTAL);

    prep_merged<<<PREP_BLKS, 256>>>(x, weight, gate, out);
    trix_hmma<<<dim3(8, 32, 4), 128, SMEM_TOTAL>>>(scales, out);
}

// round 13
// speedup vs baseline: 1.0516x; 1.0516x over previous
#include <cuda_runtime.h>
#include <cuda_fp16.h>
#include <cstdint>

// ---------------------------------------------------------------------------
// TriXLinear (sm_103 baseline PTX; tensor path = mma.sync m16n8k16 f16).
//   out = (x @ sign(W)^T) * scales * gate_mask
// x -> fp16 (norm rel err ~2.1e-4), W -> +-1 fp16 (exact). Gated-row GEMM.
// R13: recombination of proven parts.
//  - compact: 8 parallel per-part blocks (~2us, no serialization)
//  - prep: ONE merged kernel = gather+quant (f32 x -> swizzled fp16 A tiles,
//    part-prefix from g_cntp) | sign_w | zero-ungated
//  - GEMM: R6 mainloop exactly (bulk-TMA A+B, producer-only empty wait,
//    warp 64x64, block 128x128, 3 stages, 2 CTAs/SM); prologue rebuilds
//    srow from per-part counters; epilogue reads srow from smem.
// ---------------------------------------------------------------------------

#define MDIM 4096
#define NDIM 4096
#define KDIM 4096

#define NKT 64                          // K stages (64 fp16 = 128B rows)
#define STAGES 3
#define STAGE_BYTES 32768               // A 16K + B 16K
#define SMEM_SC   64                    // scales (512B)
#define SMEM_SROW 576                   // gathered row ids (512B)
#define SMEM_PRE  1088                  // part prefix (9 ints)
#define SMEM_ST   2048
#define SMEM_TOTAL (SMEM_ST + STAGES * STAGE_BYTES)   // 100352 -> 2 CTAs/SM
// mbarriers: full[s] at sb+8s, empty[s] at sb+24+8s  (s = 0..2)

// merged-prep partition
#define GATHER_BLKS 2048                // 32 mblk x 4 t x 16 kg
#define SIGNW_BLKS  8192
#define ZERO_BLKS   16384
#define PREP_BLKS   (GATHER_BLKS + SIGNW_BLKS + ZERO_BLKS)

// ------------------------------- scratch -----------------------------------
__device__ __align__(1024) unsigned char g_Wt[(size_t)32 * 1024 * 1024];
__device__ __align__(1024) unsigned char g_At[(size_t)128 * 1024 * 1024];
__device__ int g_cntp[4][8];            // per-tile per-part gated-row counts
__device__ int g_rows_part[4][8][512];  // per-part compacted row ids

// ------------------------------ PTX helpers --------------------------------
__device__ __forceinline__ uint32_t smem_u32(const void* p) {
    uint32_t a;
    asm("{ .reg .u64 t; cvta.to.shared.u64 t, %1; cvt.u32.u64 %0, t; }"
        : "=r"(a) : "l"(p));
    return a;
}
__device__ __forceinline__ uint32_t elect_one() {
    uint32_t p;
    asm volatile("{ .reg .pred p; elect.sync _|p, 0xFFFFFFFF; selp.b32 %0,1,0,p; }"
                 : "=r"(p));
    return p;
}
__device__ __forceinline__ void mbar_init(uint32_t mb, uint32_t cnt) {
    asm volatile("mbarrier.init.shared.b64 [%0], %1;" :: "r"(mb), "r"(cnt) : "memory");
}
__device__ __forceinline__ void mbar_expect_tx(uint32_t mb, uint32_t bytes) {
    asm volatile("mbarrier.arrive.expect_tx.shared.b64 _, [%0], %1;"
                 :: "r"(mb), "r"(bytes) : "memory");
}
__device__ __forceinline__ void mbar_arrive(uint32_t mb) {
    asm volatile("mbarrier.arrive.shared.b64 _, [%0];" :: "r"(mb) : "memory");
}
__device__ __forceinline__ void mbar_wait(uint32_t mb, uint32_t parity) {
    asm volatile(
        "{\n\t.reg .pred P;\n\t"
        "WL_%=:\n\t"
        "mbarrier.try_wait.parity.acquire.cta.shared::cta.b64 P, [%0], %1, 0x989680;\n\t"
        "@P bra.uni WD_%=;\n\t"
        "bra.uni WL_%=;\n\t"
        "WD_%=:\n\t}"
        :: "r"(mb), "r"(parity) : "memory");
}
__device__ __forceinline__ void bulk_g2s(uint32_t dst, const void* src,
                                         uint32_t bytes, uint32_t mb) {
    asm volatile(
        "cp.async.bulk.shared::cta.global.mbarrier::complete_tx::bytes "
        "[%0], [%1], %2, [%3];"
        :: "r"(dst), "l"(src), "r"(bytes), "r"(mb) : "memory");
}
__device__ __forceinline__ void ldm_x4(uint32_t* r, uint32_t addr) {
    asm volatile("ldmatrix.sync.aligned.m8n8.x4.shared.b16 {%0,%1,%2,%3}, [%4];"
                 : "=r"(r[0]), "=r"(r[1]), "=r"(r[2]), "=r"(r[3]) : "r"(addr));
}
__device__ __forceinline__ void hmma(float* c, const uint32_t* a,
                                     uint32_t b0, uint32_t b1) {
    asm volatile(
        "mma.sync.aligned.m16n8k16.row.col.f32.f16.f16.f32 "
        "{%0,%1,%2,%3}, {%4,%5,%6,%7}, {%8,%9}, {%0,%1,%2,%3};"
        : "+f"(c[0]), "+f"(c[1]), "+f"(c[2]), "+f"(c[3])
        : "r"(a[0]), "r"(a[1]), "r"(a[2]), "r"(a[3]), "r"(b0), "r"(b1));
}

// --------------------------- compact (8 blocks) -----------------------------
// part p handles rows [p*512, (p+1)*512); per-part counters, no cross-block
// atomics, so no zeroing dependency and no serialization.
__global__ void compact_parts(const int* __restrict__ gate) {
    const int p = blockIdx.x;
    __shared__ int scnt[4];
    int tid = threadIdx.x;
    if (tid < 4) scnt[tid] = 0;
    __syncthreads();
    int lane = tid & 31;
#pragma unroll
    for (int h = 0; h < 2; h++) {
        int r = p * 512 + h * 256 + tid;
#pragma unroll
        for (int t = 0; t < 4; t++) {
            bool pred = (gate[r * 4 + t] != 0);
            unsigned mask = __ballot_sync(0xFFFFFFFFu, pred);
            int cnt = __popc(mask);
            int base = 0;
            if (lane == 0 && cnt) base = atomicAdd(&scnt[t], cnt);
            base = __shfl_sync(0xFFFFFFFFu, base, 0);
            if (pred) {
                int rank = __popc(mask & ((1u << lane) - 1u));
                g_rows_part[t][p][base + rank] = r;
            }
        }
    }
    __syncthreads();
    if (tid < 4) g_cntp[tid][p] = scnt[tid];
}

// ------------------------------ merged prep ---------------------------------
// blockIdx.x partition:
//   [0, 2048)     gather+quant: gated f32 x rows -> fp16 swizzled A tiles
//   [2048, 10240) sign_w -> fp16 swizzled tiles
//   [10240, ...)  zero ungated (row, tile) out blocks
__global__ __launch_bounds__(256) void prep_merged(
    const float* __restrict__ x,
    const float* __restrict__ w,
    const int* __restrict__ gate,
    float* __restrict__ out) {
    const int b = blockIdx.x;
    const int tid = threadIdx.x;

    if (b < GATHER_BLKS) {
        int mblk = b & 31, t = (b >> 5) & 3, kg = b >> 7;
        __shared__ int pre[9];
        __shared__ int srow[128];
        if (tid == 0) {
            int acc = 0;
#pragma unroll
            for (int p = 0; p < 8; p++) { pre[p] = acc; acc += g_cntp[t][p]; }
            pre[8] = acc;
        }
        __syncthreads();
        const int cnt = pre[8];
        if (mblk * 128 >= cnt || cnt == 0) return;
        if (tid < 128) {
            int gidx = mblk * 128 + tid;
            if (gidx >= cnt) gidx = cnt - 1;
            int p = 0;
#pragma unroll
            for (int q = 1; q < 8; q++) p += (gidx >= pre[q]) ? 1 : 0;
            srow[tid] = g_rows_part[t][p][gidx - pre[p]];
        }
        __syncthreads();
        size_t base = ((size_t)(t * 32 + mblk)) << 20;
        int r = tid >> 3, c = tid & 7;        // 32 rows x 8 chunks / pass
#pragma unroll
        for (int kb = 0; kb < 4; kb++) {
            int kblk = kg * 4 + kb;
            size_t db = base + ((size_t)kblk << 14);
#pragma unroll
            for (int rp = 0; rp < 4; rp++) {
                int rr = r + rp * 32;
                const float4* src = reinterpret_cast<const float4*>(
                    x + (size_t)srow[rr] * KDIM + kblk * 64 + c * 8);
                float4 v0 = src[0], v1 = src[1];
                __half h[8];
                h[0] = __float2half_rn(v0.x); h[1] = __float2half_rn(v0.y);
                h[2] = __float2half_rn(v0.z); h[3] = __float2half_rn(v0.w);
                h[4] = __float2half_rn(v1.x); h[5] = __float2half_rn(v1.y);
                h[6] = __float2half_rn(v1.z); h[7] = __float2half_rn(v1.w);
                size_t dd = db + (size_t)rr * 128 + ((size_t)(c ^ (rr & 7)) << 4);
                *reinterpret_cast<uint4*>(g_At + dd) = *reinterpret_cast<uint4*>(h);
            }
        }
    } else if (b < GATHER_BLKS + SIGNW_BLKS) {
        size_t idx = (size_t)(b - GATHER_BLKS) * 256 + tid;   // *8 elems
        int row = (int)(idx >> 9);
        int k0  = ((int)idx & 511) * 8;
        const float4* pp = reinterpret_cast<const float4*>(w + (size_t)row * KDIM + k0);
        float4 v0 = pp[0], v1 = pp[1];
        float f[8] = {v0.x, v0.y, v0.z, v0.w, v1.x, v1.y, v1.z, v1.w};
        __half s[8];
#pragma unroll
        for (int j = 0; j < 8; j++)
            s[j] = __float2half_rn((f[j] > 0.f) ? 1.f : ((f[j] < 0.f) ? -1.f : 0.f));
        int nb = row >> 7, r = row & 127, kblk = k0 >> 6;
        int c = (k0 & 63) >> 3;
        size_t off = (((size_t)(nb * 64 + kblk)) << 14) +
                     (size_t)r * 128 + ((size_t)(c ^ (r & 7)) << 4);
        *reinterpret_cast<uint4*>(g_Wt + off) = *reinterpret_cast<uint4*>(s);
    } else {
        int bid = b - (GATHER_BLKS + SIGNW_BLKS);   // 16384
        int r = bid >> 2, t = bid & 3;
        if (gate[r * 4 + t] != 0) return;
        float4 z = {0.f, 0.f, 0.f, 0.f};
        reinterpret_cast<float4*>(out + (size_t)r * NDIM + t * 1024)[tid] = z;
    }
}

// ------------------------------ GEMM kernel ---------------------------------
// grid (8 nblk, 32 mblk, 4 t), 128 threads, warp grid 2(M) x 2(N), warp 64x64.
// R6 mainloop; prologue rebuilds srow from per-part counters for the epilogue.

__global__ __launch_bounds__(128, 2) void trix_hmma(
    const float* __restrict__ scales,
    float* __restrict__ out) {
    const int t = blockIdx.z, mblk = blockIdx.y, nblk = blockIdx.x;

    extern __shared__ char smem[];
    const uint32_t sb = smem_u32(smem);
    const int tid = threadIdx.x;
    const int warp = tid >> 5, lane = tid & 31;
    const int wm = warp >> 1, wn = warp & 1;
    const int n0 = t * 1024 + nblk * 128;
    const int nb = t * 8 + nblk;

    int* pre = reinterpret_cast<int*>(smem + SMEM_PRE);
    int* srow = reinterpret_cast<int*>(smem + SMEM_SROW);

    reinterpret_cast<float*>(smem + SMEM_SC)[tid] = scales[n0 + tid];
    if (tid == 0) {
        int acc = 0;
#pragma unroll
        for (int p = 0; p < 8; p++) { pre[p] = acc; acc += g_cntp[t][p]; }
        pre[8] = acc;
#pragma unroll
        for (int s = 0; s < STAGES; s++) {
            mbar_init(sb + 8u * s, 1);        // full: TMA tx
            mbar_init(sb + 24u + 8u * s, 4);  // empty: 4 warp arrivals
        }
    }
    __syncthreads();

    const int cnt = pre[8];
    if (mblk * 128 >= cnt || cnt == 0) return;

    {   // srow for epilogue (row ids of this mblk's gathered rows)
        int gidx = mblk * 128 + tid;
        if (gidx >= cnt) gidx = cnt - 1;
        int p = 0;
#pragma unroll
        for (int q = 1; q < 8; q++) p += (gidx >= pre[q]) ? 1 : 0;
        srow[tid] = g_rows_part[t][p][gidx - pre[p]];
    }
    __syncthreads();

    const unsigned char* aSrc = g_At + (((size_t)(t * 32 + mblk)) << 20);
    const unsigned char* bSrc = g_Wt + ((size_t)nb << 20);

    auto fill = [&](int s, int kt) {
        uint32_t mb = sb + 8u * s;
        uint32_t st = sb + SMEM_ST + s * STAGE_BYTES;
        mbar_expect_tx(mb, STAGE_BYTES);
        bulk_g2s(st,         aSrc + ((size_t)kt << 14), 16384, mb);
        bulk_g2s(st + 16384, bSrc + ((size_t)kt << 14), 16384, mb);
    };
    const bool prod = (warp == 0) && elect_one();
    if (prod) {
#pragma unroll
        for (int s = 0; s < STAGES; s++) fill(s, s);
    }

    // ldmatrix addressing
    int aR[4], bR[4];
#pragma unroll
    for (int ms = 0; ms < 4; ms++) aR[ms] = wm * 64 + ms * 16 + (lane & 15);
    const int aCadd = lane >> 4;
#pragma unroll
    for (int nq = 0; nq < 4; nq++)
        bR[nq] = wn * 64 + nq * 16 + (lane & 7) + ((lane >> 4) << 3);
    const int bCadd = (lane >> 3) & 1;

    float d[4][8][4];
#pragma unroll
    for (int a = 0; a < 4; a++)
#pragma unroll
        for (int b = 0; b < 8; b++)
#pragma unroll
            for (int c = 0; c < 4; c++) d[a][b][c] = 0.f;

    for (int kt = 0; kt < NKT; kt++) {
        const int s = kt % 3;
        const uint32_t ph = (uint32_t)((kt / 3) & 1);
        mbar_wait(sb + 8u * s, ph);                       // data ready
        const uint32_t st = sb + SMEM_ST + s * STAGE_BYTES;
#pragma unroll
        for (int ks = 0; ks < 4; ks++) {
            uint32_t a[4][4], bf[4][4];
#pragma unroll
            for (int ms = 0; ms < 4; ms++) {
                uint32_t off = aR[ms] * 128 +
                               (((ks * 2 + aCadd) ^ (aR[ms] & 7)) << 4);
                ldm_x4(a[ms], st + off);
            }
#pragma unroll
            for (int nq = 0; nq < 4; nq++) {
                uint32_t off = bR[nq] * 128 +
                               (((ks * 2 + bCadd) ^ (bR[nq] & 7)) << 4);
                ldm_x4(bf[nq], st + 16384 + off);
            }
#pragma unroll
            for (int ms = 0; ms < 4; ms++)
#pragma unroll
                for (int nq = 0; nq < 4; nq++) {
                    hmma(d[ms][nq * 2],     a[ms], bf[nq][0], bf[nq][1]);
                    hmma(d[ms][nq * 2 + 1], a[ms], bf[nq][2], bf[nq][3]);
                }
        }
        if (elect_one()) mbar_arrive(sb + 24u + 8u * s);  // warp consumed
        if (prod && kt + STAGES < NKT) {
            mbar_wait(sb + 24u + 8u * s, ph);             // all 4 consumed
            fill(s, kt + STAGES);
        }
    }

    // epilogue: out = acc * scales[col] for gated rows (srow in smem)
    const float* sSc = reinterpret_cast<const float*>(smem + SMEM_SC);
#pragma unroll
    for (int ms = 0; ms < 4; ms++) {
#pragma unroll
        for (int half = 0; half < 2; half++) {
            int j = wm * 64 + ms * 16 + (lane >> 2) + half * 8;
            if (mblk * 128 + j >= cnt) continue;
            int row = srow[j];
            float* orow = out + (size_t)row * NDIM + n0;
#pragma unroll
            for (int ns = 0; ns < 8; ns++) {
                int col = wn * 64 + ns * 8 + (lane & 3) * 2;
                float2 v;
                v.x = d[ms][ns][half * 2]     * sSc[col];
                v.y = d[ms][ns][half * 2 + 1] * sSc[col + 1];
                *reinterpret_cast<float2*>(orow + col) = v;
            }
        }
    }
}

// ------------------------------ launch --------------------------------------

extern "C" void kernel_launch(void* const* d_in, const int* in_sizes, int n_in,
                              void* d_out, int out_size) {
    const float* x      = (const float*)d_in[0];
    const int*   gate   = (const int*)d_in[1];
    const float* weight = (const float*)d_in[2];
    const float* scales = (const float*)d_in[3];
    float* out = (float*)d_out;

    cudaFuncSetAttribute(trix_hmma,
                         cudaFuncAttributeMaxDynamicSharedMemorySize, SMEM_TOTAL);

    compact_parts<<<8, 256>>>(gate);
    prep_merged<<<PREP_BLKS, 256>>>(x, weight, gate, out);
    trix_hmma<<<dim3(8, 32, 4), 128, SMEM_TOTAL>>>(scales, out);
}